// round 6
// baseline (speedup 1.0000x reference)
#include <cuda_runtime.h>
#include <cstdint>

#define NN 512000       // nodes = 512 * 1000
#define NE 8192000      // edges per branch
#define NB 512          // batch
#define NS 1000         // stations
#define NH 64           // ff hidden
#define NA 1024         // actions
#define EPSF 1e-5f

#define TB 256
#define GN 2000                 // 2000 * 256 = NN exactly
#define STATS_BLKS 1024
#define EDGE_BLKS8 4000         // 4000 * 256 * 8 = NE exactly

// ---------------- scratch ----------------------------------------------------
__device__ float    g_stats[3][16];        // per branch: sum[8], sumsq[8]
__device__ unsigned g_deg[3][NN];          // edge-count per dst (no self loop)
__device__ float4   g_z1[3][NN];           // xw * dinv
__device__ float4   g_acc1[3][NN];         // conv1 accumulator (init = self loop)
__device__ float    g_z2[3][NN];
__device__ float    g_acc2[3][NN];
__device__ float    g_hidden[NB][NH];      // [512, 64]

// ---------------- device helpers ---------------------------------------------

// edge phases: 0 = deg histogram, 1 = conv1 scatter, 2 = conv2 scatter
__device__ __forceinline__ void edgeWork(int phase, int br,
                                         const int* __restrict__ ei, int blk,
                                         int tid) {
    int base = blk * 2048 + tid * 8;
    if (phase == 0) {
        int4 a = __ldg((const int4*)(ei + NE + base));
        int4 b = __ldg((const int4*)(ei + NE + base + 4));
        atomicAdd(&g_deg[br][a.x], 1u);
        atomicAdd(&g_deg[br][a.y], 1u);
        atomicAdd(&g_deg[br][a.z], 1u);
        atomicAdd(&g_deg[br][a.w], 1u);
        atomicAdd(&g_deg[br][b.x], 1u);
        atomicAdd(&g_deg[br][b.y], 1u);
        atomicAdd(&g_deg[br][b.z], 1u);
        atomicAdd(&g_deg[br][b.w], 1u);
    } else if (phase == 1) {
        int4 sa = __ldg((const int4*)(ei + base));
        int4 sb = __ldg((const int4*)(ei + base + 4));
        int4 da = __ldg((const int4*)(ei + NE + base));
        int4 db = __ldg((const int4*)(ei + NE + base + 4));
        float4 z0 = __ldg(&g_z1[br][sa.x]);
        float4 z1 = __ldg(&g_z1[br][sa.y]);
        float4 z2 = __ldg(&g_z1[br][sa.z]);
        float4 z3 = __ldg(&g_z1[br][sa.w]);
        float4 z4 = __ldg(&g_z1[br][sb.x]);
        float4 z5 = __ldg(&g_z1[br][sb.y]);
        float4 z6 = __ldg(&g_z1[br][sb.z]);
        float4 z7 = __ldg(&g_z1[br][sb.w]);
        atomicAdd(&g_acc1[br][da.x], z0);
        atomicAdd(&g_acc1[br][da.y], z1);
        atomicAdd(&g_acc1[br][da.z], z2);
        atomicAdd(&g_acc1[br][da.w], z3);
        atomicAdd(&g_acc1[br][db.x], z4);
        atomicAdd(&g_acc1[br][db.y], z5);
        atomicAdd(&g_acc1[br][db.z], z6);
        atomicAdd(&g_acc1[br][db.w], z7);
    } else {
        int4 sa = __ldg((const int4*)(ei + base));
        int4 sb = __ldg((const int4*)(ei + base + 4));
        int4 da = __ldg((const int4*)(ei + NE + base));
        int4 db = __ldg((const int4*)(ei + NE + base + 4));
        float v0 = __ldg(&g_z2[br][sa.x]);
        float v1 = __ldg(&g_z2[br][sa.y]);
        float v2 = __ldg(&g_z2[br][sa.z]);
        float v3 = __ldg(&g_z2[br][sa.w]);
        float v4 = __ldg(&g_z2[br][sb.x]);
        float v5 = __ldg(&g_z2[br][sb.y]);
        float v6 = __ldg(&g_z2[br][sb.z]);
        float v7 = __ldg(&g_z2[br][sb.w]);
        atomicAdd(&g_acc2[br][da.x], v0);
        atomicAdd(&g_acc2[br][da.y], v1);
        atomicAdd(&g_acc2[br][da.z], v2);
        atomicAdd(&g_acc2[br][da.w], v3);
        atomicAdd(&g_acc2[br][db.x], v4);
        atomicAdd(&g_acc2[br][db.y], v5);
        atomicAdd(&g_acc2[br][db.z], v6);
        atomicAdd(&g_acc2[br][db.w], v7);
    }
}

// node phase 0: z1 = (norm(x)@W1)*dinv with the GraphNorm affine folded in.
__device__ __forceinline__ void nodeZ1(const float* __restrict__ x,
                                       const float* __restrict__ nw,
                                       const float* __restrict__ nbp,
                                       const float* __restrict__ nms,
                                       const float* __restrict__ W1,
                                       int br, int blk, int tid,
                                       float* sA, float* sD) {
    if (tid == 0) {
        const float inv = 1.0f / (float)NN;
        float a[8], d[8];
#pragma unroll
        for (int i = 0; i < 8; i++) {
            float mean = g_stats[br][i] * inv;
            float m2   = g_stats[br][8 + i] * inv;
            float c    = mean * nms[i];
            float var  = m2 - 2.f * c * mean + c * c;
            float ai   = nw[i] * rsqrtf(var + EPSF);
            a[i] = ai;
            d[i] = nbp[i] - c * ai;
        }
#pragma unroll
        for (int j = 0; j < 4; j++) {
            float dv = 0.f;
#pragma unroll
            for (int i = 0; i < 8; i++) {
                sA[i * 4 + j] = a[i] * W1[i * 4 + j];
                dv += d[i] * W1[i * 4 + j];
            }
            sD[j] = dv;
        }
    }
    __syncthreads();
    int n = blk * TB + tid;
    const float4* p = (const float4*)(x + (size_t)n * 8);
    float4 a = __ldg(p), b = __ldg(p + 1);
    float v[8] = {a.x, a.y, a.z, a.w, b.x, b.y, b.z, b.w};
    float dinv = rsqrtf((float)(g_deg[br][n] + 1u));
    float o[4];
#pragma unroll
    for (int j = 0; j < 4; j++) {
        float acc = sD[j];
#pragma unroll
        for (int i = 0; i < 8; i++) acc += v[i] * sA[i * 4 + j];
        o[j] = acc * dinv;
    }
    float4 z = make_float4(o[0], o[1], o[2], o[3]);
    g_z1[br][n]  = z;
    g_acc1[br][n] = z;
}

// node phase 1: h1 = relu(dinv*acc1+b1); z2 = (h1.w2)*dinv; acc2 init = z2
__device__ __forceinline__ void nodeH1Z2(const float* __restrict__ b1,
                                         const float* __restrict__ w2,
                                         int br, int blk, int tid) {
    int n = blk * TB + tid;
    float dinv = rsqrtf((float)(g_deg[br][n] + 1u));
    float4 acc = g_acc1[br][n];
    float h0 = fmaxf(fmaf(dinv, acc.x, b1[0]), 0.f);
    float h1 = fmaxf(fmaf(dinv, acc.y, b1[1]), 0.f);
    float h2 = fmaxf(fmaf(dinv, acc.z, b1[2]), 0.f);
    float h3 = fmaxf(fmaf(dinv, acc.w, b1[3]), 0.f);
    float z2 = (h0 * w2[0] + h1 * w2[1] + h2 * w2[2] + h3 * w2[3]) * dinv;
    g_z2[br][n]  = z2;
    g_acc2[br][n] = z2;
}

// ---------------- kernels ----------------------------------------------------

__global__ void zeroK() {
    int i = blockIdx.x * blockDim.x + threadIdx.x;
    if (i < 3 * NN) ((unsigned*)g_deg)[i] = 0u;
    if (i < 48)     ((float*)g_stats)[i] = 0.f;
}

// stats for all 3 branches + deg histogram for branch 0
__global__ void statsAllDeg0K(const float* __restrict__ x0,
                              const float* __restrict__ x1,
                              const float* __restrict__ x2,
                              const int* __restrict__ e0) {
    if (blockIdx.x < 3 * STATS_BLKS) {
        int br  = blockIdx.x / STATS_BLKS;
        int blk = blockIdx.x - br * STATS_BLKS;
        const float* x = br == 0 ? x0 : (br == 1 ? x1 : x2);
        float s[8], q[8];
#pragma unroll
        for (int i = 0; i < 8; i++) { s[i] = 0.f; q[i] = 0.f; }
        int stride = STATS_BLKS * TB;
        for (int n = blk * TB + threadIdx.x; n < NN; n += stride) {
            const float4* p = (const float4*)(x + (size_t)n * 8);
            float4 a = __ldg(p), b = __ldg(p + 1);
            float v[8] = {a.x, a.y, a.z, a.w, b.x, b.y, b.z, b.w};
#pragma unroll
            for (int i = 0; i < 8; i++) { s[i] += v[i]; q[i] += v[i] * v[i]; }
        }
#pragma unroll
        for (int i = 0; i < 8; i++) {
#pragma unroll
            for (int o = 16; o; o >>= 1) {
                s[i] += __shfl_down_sync(0xffffffffu, s[i], o);
                q[i] += __shfl_down_sync(0xffffffffu, q[i], o);
            }
        }
        __shared__ float sh[16];
        if (threadIdx.x < 16) sh[threadIdx.x] = 0.f;
        __syncthreads();
        if ((threadIdx.x & 31) == 0) {
#pragma unroll
            for (int i = 0; i < 8; i++) {
                atomicAdd(&sh[i], s[i]);
                atomicAdd(&sh[8 + i], q[i]);
            }
        }
        __syncthreads();
        if (threadIdx.x < 16) atomicAdd(&g_stats[br][threadIdx.x], sh[threadIdx.x]);
    } else {
        edgeWork(0, 0, e0, blockIdx.x - 3 * STATS_BLKS, threadIdx.x);
    }
}

// generic pipelined stage: up to 2 edge jobs + 2 node jobs, by blockIdx range
__global__ void stageK(int e0p, int e0b, int e1p, int e1b,
                       int n0p, int n0b, int n1p, int n1b,
                       const int* __restrict__ e0, const int* __restrict__ e1,
                       const int* __restrict__ e2,
                       const float* __restrict__ x0, const float* __restrict__ x1,
                       const float* __restrict__ x2,
                       const float* __restrict__ nw, const float* __restrict__ nbp,
                       const float* __restrict__ nms, const float* __restrict__ W1,
                       const float* __restrict__ b1, const float* __restrict__ w2) {
    __shared__ float sA[32];
    __shared__ float sD[4];
    const int* ei[3] = {e0, e1, e2};
    const float* x[3] = {x0, x1, x2};
    int bx = blockIdx.x;
    if (bx < EDGE_BLKS8) {
        edgeWork(e0p, e0b, ei[e0b], bx, threadIdx.x);
        return;
    }
    bx -= EDGE_BLKS8;
    if (e1p >= 0) {
        if (bx < EDGE_BLKS8) {
            edgeWork(e1p, e1b, ei[e1b], bx, threadIdx.x);
            return;
        }
        bx -= EDGE_BLKS8;
    }
    if (n0p >= 0) {
        if (bx < GN) {
            if (n0p == 0) nodeZ1(x[n0b], nw, nbp, nms, W1, n0b, bx, threadIdx.x, sA, sD);
            else          nodeH1Z2(b1, w2, n0b, bx, threadIdx.x);
            return;
        }
        bx -= GN;
    }
    if (n1p >= 0) {
        if (n1p == 0) nodeZ1(x[n1b], nw, nbp, nms, W1, n1b, bx, threadIdx.x, sA, sD);
        else          nodeH1Z2(b1, w2, n1b, bx, threadIdx.x);
    }
}

// fused conv2 epilogue + concat + ff1
__global__ void ff1K(const float* __restrict__ b2, const float* __restrict__ w,
                     const float* __restrict__ bias) {
    __shared__ float row[3 * NS];
    __shared__ float part[4][NH];
    int b = blockIdx.x;
    for (int k = threadIdx.x; k < 3 * NS; k += blockDim.x) {
        int br = k / NS;
        int s  = k - br * NS;
        int n  = b * NS + s;
        float dinv = rsqrtf((float)(g_deg[br][n] + 1u));
        row[k] = fmaxf(fmaf(dinv, g_acc2[br][n], b2[0]), 0.f);
    }
    __syncthreads();
    int g = threadIdx.x >> 6;
    int j = threadIdx.x & 63;
    float acc = 0.f;
    int k0 = g * 750, k1 = k0 + 750;
    for (int k = k0; k < k1; ++k) acc += row[k] * __ldg(w + (size_t)k * NH + j);
    part[g][j] = acc;
    __syncthreads();
    if (threadIdx.x < NH) {
        float v = part[0][threadIdx.x] + part[1][threadIdx.x] +
                  part[2][threadIdx.x] + part[3][threadIdx.x] + bias[threadIdx.x];
        g_hidden[b][threadIdx.x] = fmaxf(v, 0.f);
    }
}

// [512,64] @ [64,1024] + bias, * mask
__global__ void ff2K(const float* __restrict__ w, const float* __restrict__ bias,
                     const float* __restrict__ mask, float* __restrict__ out) {
    __shared__ float h[NH];
    int b = blockIdx.x;
    if (threadIdx.x < NH) h[threadIdx.x] = g_hidden[b][threadIdx.x];
    __syncthreads();
    for (int o = threadIdx.x; o < NA; o += blockDim.x) {
        float acc = bias[o];
#pragma unroll 8
        for (int k = 0; k < NH; k++) acc += h[k] * __ldg(w + (size_t)k * NA + o);
        out[(size_t)b * NA + o] = acc * mask[(size_t)b * NA + o];
    }
}

// ---------------- launch ------------------------------------------------------

extern "C" void kernel_launch(void* const* d_in, const int* in_sizes, int n_in,
                              void* d_out, int out_size) {
    const float* x0 = (const float*)d_in[0];
    const float* x1 = (const float*)d_in[1];
    const float* x2 = (const float*)d_in[2];
    const int* e0 = (const int*)d_in[3];
    const int* e1 = (const int*)d_in[4];
    const int* e2 = (const int*)d_in[5];
    const float* mask = (const float*)d_in[6];
    const float* nw  = (const float*)d_in[7];
    const float* nb  = (const float*)d_in[8];
    const float* nms = (const float*)d_in[9];
    const float* W1  = (const float*)d_in[10];
    const float* b1  = (const float*)d_in[11];
    const float* W2  = (const float*)d_in[12];
    const float* b2  = (const float*)d_in[13];
    const float* wf1 = (const float*)d_in[14];
    const float* bf1 = (const float*)d_in[15];
    const float* wf2 = (const float*)d_in[16];
    const float* bf2 = (const float*)d_in[17];
    float* out = (float*)d_out;

#define STAGE(g, args...) stageK<<<(g), TB>>>(args, e0, e1, e2, x0, x1, x2, \
                                              nw, nb, nms, W1, b1, W2)

    zeroK<<<(3 * NN + TB - 1) / TB, TB>>>();
    // L2: stats(all) + deg(0)
    statsAllDeg0K<<<3 * STATS_BLKS + EDGE_BLKS8, TB>>>(x0, x1, x2, e0);
    // L3: deg(1) + z1(0)
    STAGE(EDGE_BLKS8 + GN,                0,1, -1,0,  0,0, -1,0);
    // L4: deg(2) + scat1(0) + z1(1)
    STAGE(2 * EDGE_BLKS8 + GN,            0,2,  1,0,  0,1, -1,0);
    // L5: scat1(1) + h1z2(0) + z1(2)
    STAGE(EDGE_BLKS8 + 2 * GN,            1,1, -1,0,  1,0,  0,2);
    // L6: scat1(2) + scat2(0) + h1z2(1)
    STAGE(2 * EDGE_BLKS8 + GN,            1,2,  2,0,  1,1, -1,0);
    // L7: scat2(1) + h1z2(2)
    STAGE(EDGE_BLKS8 + GN,                2,1, -1,0,  1,2, -1,0);
    // L8: scat2(2)
    STAGE(EDGE_BLKS8,                     2,2, -1,0, -1,0, -1,0);
#undef STAGE

    ff1K<<<NB, TB>>>(b2, wf1, bf1);
    ff2K<<<NB, TB>>>(wf2, bf2, mask, out);
}